// round 15
// baseline (speedup 1.0000x reference)
#include <cuda_runtime.h>
#include <cuda_bf16.h>
#include <cstdint>

#define MAX_ATOMS 40000
#define MAX_EDGES 640000
#define NFM 128

// ---------------------------------------------------------------------------
// Scratch
// ---------------------------------------------------------------------------
__device__ float    g_f[(size_t)MAX_ATOMS * NFM];     // f = x @ W_in
__device__ float    g_conv[(size_t)MAX_ATOMS * NFM];  // segment-summed conv
// Pre-packed B fragments in mma.m16n8k16 register order.
// [matrix: 0=Win 1=Wout][term: 0=hi 1=lo][ ((t*8+k)*32+lane)*2 + reg ]
__device__ uint32_t g_Bfrag[2][2][8192];

// ---------------------------------------------------------------------------
__device__ __forceinline__ void split_pair(float v0, float v1,
                                           uint32_t& hp, uint32_t& lp) {
    __nv_bfloat16 h0 = __float2bfloat16(v0);
    __nv_bfloat16 h1 = __float2bfloat16(v1);
    __nv_bfloat16 l0 = __float2bfloat16(v0 - __bfloat162float(h0));
    __nv_bfloat16 l1 = __float2bfloat16(v1 - __bfloat162float(h1));
    hp = (uint32_t)__bfloat16_as_ushort(h0) | ((uint32_t)__bfloat16_as_ushort(h1) << 16);
    lp = (uint32_t)__bfloat16_as_ushort(l0) | ((uint32_t)__bfloat16_as_ushort(l1) << 16);
}

__device__ __forceinline__ void mma16816(float* c, const uint32_t* a,
                                         uint32_t b0, uint32_t b1) {
    asm volatile(
        "mma.sync.aligned.m16n8k16.row.col.f32.bf16.bf16.f32 "
        "{%0,%1,%2,%3}, {%4,%5,%6,%7}, {%8,%9}, {%0,%1,%2,%3};"
        : "+f"(c[0]), "+f"(c[1]), "+f"(c[2]), "+f"(c[3])
        : "r"(a[0]), "r"(a[1]), "r"(a[2]), "r"(a[3]), "r"(b0), "r"(b1));
}

__device__ __forceinline__ uint32_t smem_u32(const void* p) {
    uint32_t a;
    asm("{ .reg .u64 t; cvta.to.shared.u64 t, %1; cvt.u32.u64 %0, t; }"
        : "=r"(a) : "l"(p));
    return a;
}

__device__ __forceinline__ void cp_async16(uint32_t smem_addr, const void* gptr) {
    asm volatile("cp.async.cg.shared.global [%0], [%1], 16;"
                 :: "r"(smem_addr), "l"(gptr) : "memory");
}
#define CP_COMMIT() asm volatile("cp.async.commit_group;" ::: "memory")
#define CP_WAIT2()  asm volatile("cp.async.wait_group 2;" ::: "memory")

// ---------------------------------------------------------------------------
// Prep: pack weights into B-fragment order, split hi/lo. W is [K,N] row-major.
// ---------------------------------------------------------------------------
__global__ void prep_weights_kernel(const float* __restrict__ W_in,
                                    const float* __restrict__ W_out)
{
    int id = blockIdx.x * blockDim.x + threadIdx.x;   // 0..32767
    int reg  = id & 1;
    int lane = (id >> 1) & 31;
    int k    = (id >> 6) & 7;
    int t    = (id >> 9) & 15;
    int term = (id >> 13) & 1;
    int mat  = (id >> 14) & 1;

    const float* W = mat ? W_out : W_in;
    int kr = k * 16 + (lane & 3) * 2 + reg * 8;
    int n  = t * 8 + (lane >> 2);
    float v0 = W[(size_t)kr * 128 + n];
    float v1 = W[(size_t)(kr + 1) * 128 + n];
    uint32_t hp, lp;
    split_pair(v0, v1, hp, lp);
    g_Bfrag[mat][term][(((t * 8 + k) * 32) + lane) * 2 + reg] = term ? lp : hp;
}

// ---------------------------------------------------------------------------
// Zero g_conv (atomic targets + edgeless atoms need zeroed rows).
// ---------------------------------------------------------------------------
__global__ void zero_conv_kernel(int n_float4)
{
    int i = blockIdx.x * blockDim.x + threadIdx.x;
    if (i < n_float4)
        reinterpret_cast<float4*>(g_conv)[i] = make_float4(0.f, 0.f, 0.f, 0.f);
}

// ---------------------------------------------------------------------------
// GEMM via mma.sync: C[M,128] = A[M,128] @ W[128,128] (+bias).
// Split bf16 3-term. CTA: 64x128 tile, 8 warps (warp tile 32x32), 2 CTAs/SM.
// ---------------------------------------------------------------------------
#define A_STRIDE 136   // bf16 elems per row (bank-conflict-free)

__global__ __launch_bounds__(256, 2)
void gemm_mma_kernel(const float* __restrict__ A,
                     const uint32_t* __restrict__ Bh,
                     const uint32_t* __restrict__ Bl,
                     const float* __restrict__ bias,
                     float* __restrict__ C, int M)
{
    extern __shared__ __nv_bfloat16 sA[];     // [2][64][A_STRIDE]
    __nv_bfloat16* Ah = sA;
    __nv_bfloat16* Al = sA + 64 * A_STRIDE;

    const int tid = threadIdx.x;
    const int m0  = blockIdx.x * 64;

    // ---- stage A tile with float4 loads (8 x LDG.128 per thread) ----
#pragma unroll
    for (int it = 0; it < 8; it++) {
        int p  = tid + it * 256;              // 0..2047 float4s
        int m  = p >> 5;                      // local row 0..63
        int kq = (p & 31) << 2;               // col (multiple of 4)
        float4 v = make_float4(0.f, 0.f, 0.f, 0.f);
        if (m0 + m < M)
            v = *reinterpret_cast<const float4*>(&A[(size_t)(m0 + m) * 128 + kq]);
        uint32_t hp0, lp0, hp1, lp1;
        split_pair(v.x, v.y, hp0, lp0);
        split_pair(v.z, v.w, hp1, lp1);
        *reinterpret_cast<uint2*>(&Ah[m * A_STRIDE + kq]) = make_uint2(hp0, hp1);
        *reinterpret_cast<uint2*>(&Al[m * A_STRIDE + kq]) = make_uint2(lp0, lp1);
    }
    __syncthreads();

    const int wid  = tid >> 5;
    const int lane = tid & 31;
    const int wm   = wid & 1;
    const int wn   = wid >> 1;
    const int g    = lane >> 2;
    const int tg   = lane & 3;

    float acc[2][4][4];
#pragma unroll
    for (int mf = 0; mf < 2; mf++)
#pragma unroll
        for (int t4 = 0; t4 < 4; t4++)
#pragma unroll
            for (int i = 0; i < 4; i++) acc[mf][t4][i] = 0.f;

#pragma unroll
    for (int k = 0; k < 8; k++) {
        uint32_t ah[2][4], al[2][4];
        const int cb = k * 16 + tg * 2;
#pragma unroll
        for (int mf = 0; mf < 2; mf++) {
            int r = wm * 32 + mf * 16 + g;
            ah[mf][0] = *reinterpret_cast<const uint32_t*>(&Ah[r * A_STRIDE + cb]);
            ah[mf][1] = *reinterpret_cast<const uint32_t*>(&Ah[(r + 8) * A_STRIDE + cb]);
            ah[mf][2] = *reinterpret_cast<const uint32_t*>(&Ah[r * A_STRIDE + cb + 8]);
            ah[mf][3] = *reinterpret_cast<const uint32_t*>(&Ah[(r + 8) * A_STRIDE + cb + 8]);
            al[mf][0] = *reinterpret_cast<const uint32_t*>(&Al[r * A_STRIDE + cb]);
            al[mf][1] = *reinterpret_cast<const uint32_t*>(&Al[(r + 8) * A_STRIDE + cb]);
            al[mf][2] = *reinterpret_cast<const uint32_t*>(&Al[r * A_STRIDE + cb + 8]);
            al[mf][3] = *reinterpret_cast<const uint32_t*>(&Al[(r + 8) * A_STRIDE + cb + 8]);
        }
#pragma unroll
        for (int t4 = 0; t4 < 4; t4++) {
            int fidx = (((wn * 4 + t4) * 8 + k) * 32 + lane) * 2;
            uint32_t bh0 = __ldg(&Bh[fidx]);
            uint32_t bh1 = __ldg(&Bh[fidx + 1]);
            uint32_t bl0 = __ldg(&Bl[fidx]);
            uint32_t bl1 = __ldg(&Bl[fidx + 1]);
#pragma unroll
            for (int mf = 0; mf < 2; mf++) {
                mma16816(acc[mf][t4], ah[mf], bh0, bh1);
                mma16816(acc[mf][t4], ah[mf], bl0, bl1);
                mma16816(acc[mf][t4], al[mf], bh0, bh1);
            }
        }
    }

#pragma unroll
    for (int t4 = 0; t4 < 4; t4++) {
        int col = wn * 32 + t4 * 8 + tg * 2;
        float b0 = bias ? __ldg(&bias[col])     : 0.f;
        float b1 = bias ? __ldg(&bias[col + 1]) : 0.f;
#pragma unroll
        for (int mf = 0; mf < 2; mf++) {
            int row = m0 + wm * 32 + mf * 16 + g;
            if (row < M) {
                float2 o0 = make_float2(acc[mf][t4][0] + b0, acc[mf][t4][1] + b1);
                *reinterpret_cast<float2*>(&C[(size_t)row * 128 + col]) = o0;
            }
            if (row + 8 < M) {
                float2 o1 = make_float2(acc[mf][t4][2] + b0, acc[mf][t4][3] + b1);
                *reinterpret_cast<float2*>(&C[(size_t)(row + 8) * 128 + col]) = o1;
            }
        }
    }
}

// ---------------------------------------------------------------------------
// Edge-centric conv (R9 shape: EPW=32, GRP=4, interleaved order) with the
// w-stream moved to a depth-3 cp.async smem pipeline: 12 w-edges in flight
// per warp with ZERO register cost. Each lane copies and reads back only its
// own 16B slice, so no intra-warp sync is needed. f-gathers stay in regs.
// ---------------------------------------------------------------------------
#define EPW 32
#define GRP 4
#define DEPTH 3

__device__ __forceinline__ void flush_row(int atom, int c, const float4& acc,
                                          bool use_atomic)
{
    float* p = &g_conv[(size_t)atom * 128 + c];
    if (use_atomic) {
        atomicAdd(p + 0, acc.x);
        atomicAdd(p + 1, acc.y);
        atomicAdd(p + 2, acc.z);
        atomicAdd(p + 3, acc.w);
    } else {
        *reinterpret_cast<float4*>(p) = acc;
    }
}

__global__ __launch_bounds__(256)
void conv_edge_kernel(const float* __restrict__ w_ij,
                      const int* __restrict__ idx_j,
                      const int* __restrict__ seg_i,
                      int num_edges)
{
    // [8 warps][DEPTH][GRP edges][128 floats] = 49152 bytes
    __shared__ float sw[8 * DEPTH * GRP * 128];

    const int warp = threadIdx.x >> 5;
    const int lane = threadIdx.x & 31;
    const int c    = lane * 4;
    const int wg   = blockIdx.x * 8 + warp;
    const int kbeg = wg * EPW;
    if (kbeg >= num_edges) return;
    const int kend = min(kbeg + EPW, num_edges);

    // per-lane smem base for this warp's pipeline slot
    float* const my_sw = &sw[(warp * DEPTH * GRP) * 128];
    const uint32_t sw_base = smem_u32(&my_sw[c]);   // + buf*GRP*512 + u*512 bytes

    // ---- prologue: issue DEPTH groups of w cp.asyncs ----
#pragma unroll
    for (int d = 0; d < DEPTH; d++) {
        const int kk = kbeg + d * GRP;
#pragma unroll
        for (int u = 0; u < GRP; u++) {
            if (kk + u < kend)
                cp_async16(sw_base + (d * GRP + u) * 512,
                           &w_ij[(size_t)(kk + u) * 128 + c]);
        }
        CP_COMMIT();
    }

    int cur = __ldg(&seg_i[kbeg]);
    const int first_atom = cur;
    float4 acc = make_float4(0.f, 0.f, 0.f, 0.f);

    int k = kbeg;
    int buf = 0;
    int j[GRP], s[GRP];
    int gsz = min(GRP, kend - k);
#pragma unroll
    for (int u = 0; u < GRP; u++)
        if (u < gsz) { j[u] = __ldg(&idx_j[k + u]); s[u] = __ldg(&seg_i[k + u]); }

    while (k < kend) {
        // prefetch next group's indices/segments
        int nj[GRP], ns[GRP];
        const int nk = k + GRP;
        const int ngsz = (nk < kend) ? min(GRP, kend - nk) : 0;
#pragma unroll
        for (int u = 0; u < GRP; u++)
            if (u < ngsz) { nj[u] = __ldg(&idx_j[nk + u]); ns[u] = __ldg(&seg_i[nk + u]); }

        // f gathers for current group (register loads, long latency)
        float4 f4[GRP];
#pragma unroll
        for (int u = 0; u < GRP; u++)
            if (u < gsz)
                f4[u] = __ldg(reinterpret_cast<const float4*>(&g_f[(size_t)j[u] * 128 + c]));

        // retire oldest cp.async group, read w from smem
        CP_WAIT2();
        float4 w4[GRP];
#pragma unroll
        for (int u = 0; u < GRP; u++)
            if (u < gsz)
                w4[u] = *reinterpret_cast<const float4*>(
                    &my_sw[(buf * GRP + u) * 128 + c]);

        // issue the group DEPTH ahead into the freed buffer
        {
            const int kk = k + DEPTH * GRP;
#pragma unroll
            for (int u = 0; u < GRP; u++) {
                if (kk + u < kend)
                    cp_async16(sw_base + (buf * GRP + u) * 512,
                               &w_ij[(size_t)(kk + u) * 128 + c]);
            }
            CP_COMMIT();
        }

        // accumulate with run-break flushes (seg uniform across warp)
#pragma unroll
        for (int u = 0; u < GRP; u++) {
            if (u < gsz) {
                acc.x = fmaf(w4[u].x, f4[u].x, acc.x);
                acc.y = fmaf(w4[u].y, f4[u].y, acc.y);
                acc.z = fmaf(w4[u].z, f4[u].z, acc.z);
                acc.w = fmaf(w4[u].w, f4[u].w, acc.w);
                int nxt = -1;
                if (u + 1 < gsz)      nxt = s[u + 1];
                else if (ngsz > 0)    nxt = ns[0];
                if (nxt != cur) {
                    if (nxt >= 0) {
                        flush_row(cur, c, acc, cur == first_atom);
                        acc = make_float4(0.f, 0.f, 0.f, 0.f);
                        cur = nxt;
                    }
                }
            }
        }

#pragma unroll
        for (int u = 0; u < GRP; u++) { j[u] = nj[u]; s[u] = ns[u]; }
        k = nk;
        gsz = ngsz;
        buf = (buf + 1 == DEPTH) ? 0 : buf + 1;
    }

    // final flush: atom may span into neighboring chunks
    flush_row(cur, c, acc, true);
}

// ---------------------------------------------------------------------------
extern "C" void kernel_launch(void* const* d_in, const int* in_sizes, int n_in,
                              void* d_out, int out_size)
{
    const float* x    = (const float*)d_in[0];
    const float* wij  = (const float*)d_in[1];
    const int*   seg  = (const int*)d_in[2];
    const int*   idxj = (const int*)d_in[3];
    int base = 4;
    if (n_in >= 8 && in_sizes[4] == 1) base = 5;   // skip scalar seg_i_sum
    const float* Win  = (const float*)d_in[base];
    const float* Wout = (const float*)d_in[base + 1];
    const float* bout = (const float*)d_in[base + 2];

    int num_edges = in_sizes[2];
    int num_atoms = out_size / NFM;
    if (num_atoms > MAX_ATOMS) num_atoms = MAX_ATOMS;
    if (num_edges > MAX_EDGES) num_edges = MAX_EDGES;

    float*    f_ptr    = nullptr;
    float*    conv_ptr = nullptr;
    uint32_t* bfrag    = nullptr;
    cudaGetSymbolAddress((void**)&f_ptr, g_f);
    cudaGetSymbolAddress((void**)&conv_ptr, g_conv);
    cudaGetSymbolAddress((void**)&bfrag, g_Bfrag);

    const int SMEM_A = 2 * 64 * A_STRIDE * (int)sizeof(__nv_bfloat16);  // 34816
    cudaFuncSetAttribute(gemm_mma_kernel,
                         cudaFuncAttributeMaxDynamicSharedMemorySize, SMEM_A);

    int gblocks = (num_atoms + 63) / 64;

    // 0) pack weights into mma B fragments (hi/lo)
    prep_weights_kernel<<<128, 256>>>(Win, Wout);

    // 1) zero conv accumulator
    int nf4 = num_atoms * 32;
    zero_conv_kernel<<<(nf4 + 255) / 256, 256>>>(nf4);

    // 2) f = x @ W_in
    gemm_mma_kernel<<<gblocks, 256, SMEM_A>>>(
        x, bfrag + 0 * 8192, bfrag + 1 * 8192, nullptr, f_ptr, num_atoms);

    // 3) conv = segment_sum(w_ij * f[idx_j])   (edge-centric, cp.async pipe)
    int nwarps = (num_edges + EPW - 1) / EPW;
    conv_edge_kernel<<<(nwarps + 7) / 8, 256>>>(wij, idxj, seg, num_edges);

    // 4) out = conv @ W_out + b_out
    gemm_mma_kernel<<<gblocks, 256, SMEM_A>>>(
        conv_ptr, bfrag + 2 * 8192, bfrag + 3 * 8192, bout, (float*)d_out, num_atoms);
}

// round 16
// speedup vs baseline: 1.1551x; 1.1551x over previous
#include <cuda_runtime.h>
#include <cuda_bf16.h>
#include <cstdint>

#define MAX_ATOMS 40000
#define MAX_EDGES 640000
#define NFM 128

// ---------------------------------------------------------------------------
// Scratch
// ---------------------------------------------------------------------------
__device__ float    g_f[(size_t)MAX_ATOMS * NFM];     // f = x @ W_in
__device__ float    g_conv[(size_t)MAX_ATOMS * NFM];  // segment-summed conv
// Pre-packed B fragments in mma.m16n8k16 register order.
// [matrix: 0=Win 1=Wout][term: 0=hi 1=lo][ ((t*8+k)*32+lane)*2 + reg ]
__device__ uint32_t g_Bfrag[2][2][8192];

// ---------------------------------------------------------------------------
__device__ __forceinline__ void split_pair(float v0, float v1,
                                           uint32_t& hp, uint32_t& lp) {
    __nv_bfloat16 h0 = __float2bfloat16(v0);
    __nv_bfloat16 h1 = __float2bfloat16(v1);
    __nv_bfloat16 l0 = __float2bfloat16(v0 - __bfloat162float(h0));
    __nv_bfloat16 l1 = __float2bfloat16(v1 - __bfloat162float(h1));
    hp = (uint32_t)__bfloat16_as_ushort(h0) | ((uint32_t)__bfloat16_as_ushort(h1) << 16);
    lp = (uint32_t)__bfloat16_as_ushort(l0) | ((uint32_t)__bfloat16_as_ushort(l1) << 16);
}

__device__ __forceinline__ void mma16816(float* c, const uint32_t* a,
                                         uint32_t b0, uint32_t b1) {
    asm volatile(
        "mma.sync.aligned.m16n8k16.row.col.f32.bf16.bf16.f32 "
        "{%0,%1,%2,%3}, {%4,%5,%6,%7}, {%8,%9}, {%0,%1,%2,%3};"
        : "+f"(c[0]), "+f"(c[1]), "+f"(c[2]), "+f"(c[3])
        : "r"(a[0]), "r"(a[1]), "r"(a[2]), "r"(a[3]), "r"(b0), "r"(b1));
}

// ---------------------------------------------------------------------------
// Fused prep + zero: blocks [0,128) pack weights into B-fragment order
// (split hi/lo); blocks [128, ...) zero g_conv. One launch, overlapped.
// ---------------------------------------------------------------------------
__global__ void prep_zero_kernel(const float* __restrict__ W_in,
                                 const float* __restrict__ W_out,
                                 int n_float4)
{
    if (blockIdx.x < 128) {
        int id = blockIdx.x * 256 + threadIdx.x;      // 0..32767
        int reg  = id & 1;
        int lane = (id >> 1) & 31;
        int k    = (id >> 6) & 7;
        int t    = (id >> 9) & 15;
        int term = (id >> 13) & 1;
        int mat  = (id >> 14) & 1;

        const float* W = mat ? W_out : W_in;
        int kr = k * 16 + (lane & 3) * 2 + reg * 8;
        int n  = t * 8 + (lane >> 2);
        float v0 = W[(size_t)kr * 128 + n];
        float v1 = W[(size_t)(kr + 1) * 128 + n];
        uint32_t hp, lp;
        split_pair(v0, v1, hp, lp);
        g_Bfrag[mat][term][(((t * 8 + k) * 32) + lane) * 2 + reg] = term ? lp : hp;
    } else {
        int i = (blockIdx.x - 128) * 256 + threadIdx.x;
        if (i < n_float4)
            reinterpret_cast<float4*>(g_conv)[i] = make_float4(0.f, 0.f, 0.f, 0.f);
    }
}

// ---------------------------------------------------------------------------
// GEMM via mma.sync: C[M,128] = A[M,128] @ W[128,128] (+bias).
// Split bf16 3-term. CTA: 64x128 tile, 8 warps (warp tile 32x32), 3 CTAs/SM.
// ---------------------------------------------------------------------------
#define A_STRIDE 136   // bf16 elems per row (bank-conflict-free)

__global__ __launch_bounds__(256, 3)
void gemm_mma_kernel(const float* __restrict__ A,
                     const uint32_t* __restrict__ Bh,
                     const uint32_t* __restrict__ Bl,
                     const float* __restrict__ bias,
                     float* __restrict__ C, int M)
{
    extern __shared__ __nv_bfloat16 sA[];     // [2][64][A_STRIDE]
    __nv_bfloat16* Ah = sA;
    __nv_bfloat16* Al = sA + 64 * A_STRIDE;

    const int tid = threadIdx.x;
    const int m0  = blockIdx.x * 64;

    // ---- stage A tile with float4 loads (8 x LDG.128 per thread) ----
#pragma unroll
    for (int it = 0; it < 8; it++) {
        int p  = tid + it * 256;              // 0..2047 float4s
        int m  = p >> 5;                      // local row 0..63
        int kq = (p & 31) << 2;               // col (multiple of 4)
        float4 v = make_float4(0.f, 0.f, 0.f, 0.f);
        if (m0 + m < M)
            v = *reinterpret_cast<const float4*>(&A[(size_t)(m0 + m) * 128 + kq]);
        uint32_t hp0, lp0, hp1, lp1;
        split_pair(v.x, v.y, hp0, lp0);
        split_pair(v.z, v.w, hp1, lp1);
        *reinterpret_cast<uint2*>(&Ah[m * A_STRIDE + kq]) = make_uint2(hp0, hp1);
        *reinterpret_cast<uint2*>(&Al[m * A_STRIDE + kq]) = make_uint2(lp0, lp1);
    }
    __syncthreads();

    const int wid  = tid >> 5;
    const int lane = tid & 31;
    const int wm   = wid & 1;
    const int wn   = wid >> 1;
    const int g    = lane >> 2;
    const int tg   = lane & 3;

    float acc[2][4][4];
#pragma unroll
    for (int mf = 0; mf < 2; mf++)
#pragma unroll
        for (int t4 = 0; t4 < 4; t4++)
#pragma unroll
            for (int i = 0; i < 4; i++) acc[mf][t4][i] = 0.f;

#pragma unroll
    for (int k = 0; k < 8; k++) {
        uint32_t ah[2][4], al[2][4];
        const int cb = k * 16 + tg * 2;
#pragma unroll
        for (int mf = 0; mf < 2; mf++) {
            int r = wm * 32 + mf * 16 + g;
            ah[mf][0] = *reinterpret_cast<const uint32_t*>(&Ah[r * A_STRIDE + cb]);
            ah[mf][1] = *reinterpret_cast<const uint32_t*>(&Ah[(r + 8) * A_STRIDE + cb]);
            ah[mf][2] = *reinterpret_cast<const uint32_t*>(&Ah[r * A_STRIDE + cb + 8]);
            ah[mf][3] = *reinterpret_cast<const uint32_t*>(&Ah[(r + 8) * A_STRIDE + cb + 8]);
            al[mf][0] = *reinterpret_cast<const uint32_t*>(&Al[r * A_STRIDE + cb]);
            al[mf][1] = *reinterpret_cast<const uint32_t*>(&Al[(r + 8) * A_STRIDE + cb]);
            al[mf][2] = *reinterpret_cast<const uint32_t*>(&Al[r * A_STRIDE + cb + 8]);
            al[mf][3] = *reinterpret_cast<const uint32_t*>(&Al[(r + 8) * A_STRIDE + cb + 8]);
        }
#pragma unroll
        for (int t4 = 0; t4 < 4; t4++) {
            int fidx = (((wn * 4 + t4) * 8 + k) * 32 + lane) * 2;
            uint32_t bh0 = __ldg(&Bh[fidx]);
            uint32_t bh1 = __ldg(&Bh[fidx + 1]);
            uint32_t bl0 = __ldg(&Bl[fidx]);
            uint32_t bl1 = __ldg(&Bl[fidx + 1]);
#pragma unroll
            for (int mf = 0; mf < 2; mf++) {
                mma16816(acc[mf][t4], ah[mf], bh0, bh1);
                mma16816(acc[mf][t4], ah[mf], bl0, bl1);
                mma16816(acc[mf][t4], al[mf], bh0, bh1);
            }
        }
    }

#pragma unroll
    for (int t4 = 0; t4 < 4; t4++) {
        int col = wn * 32 + t4 * 8 + tg * 2;
        float b0 = bias ? __ldg(&bias[col])     : 0.f;
        float b1 = bias ? __ldg(&bias[col + 1]) : 0.f;
#pragma unroll
        for (int mf = 0; mf < 2; mf++) {
            int row = m0 + wm * 32 + mf * 16 + g;
            if (row < M) {
                float2 o0 = make_float2(acc[mf][t4][0] + b0, acc[mf][t4][1] + b1);
                *reinterpret_cast<float2*>(&C[(size_t)row * 128 + col]) = o0;
            }
            if (row + 8 < M) {
                float2 o1 = make_float2(acc[mf][t4][2] + b0, acc[mf][t4][3] + b1);
                *reinterpret_cast<float2*>(&C[(size_t)(row + 8) * 128 + col]) = o1;
            }
        }
    }
}

// ---------------------------------------------------------------------------
// Edge-centric conv: EXACT R9 configuration (measured local optimum).
// Each warp owns 32 consecutive edges; GRP=4 software pipeline with index
// prefetch; w/f loads interleaved in edge order; interior atoms direct-store,
// boundary atoms atomicAdd into zeroed g_conv.
// ---------------------------------------------------------------------------
#define EPW 32
#define GRP 4

__device__ __forceinline__ void flush_row(int atom, int c, const float4& acc,
                                          bool use_atomic)
{
    float* p = &g_conv[(size_t)atom * 128 + c];
    if (use_atomic) {
        atomicAdd(p + 0, acc.x);
        atomicAdd(p + 1, acc.y);
        atomicAdd(p + 2, acc.z);
        atomicAdd(p + 3, acc.w);
    } else {
        *reinterpret_cast<float4*>(p) = acc;
    }
}

__global__ __launch_bounds__(256)
void conv_edge_kernel(const float* __restrict__ w_ij,
                      const int* __restrict__ idx_j,
                      const int* __restrict__ seg_i,
                      int num_edges)
{
    const int wg   = blockIdx.x * 8 + (threadIdx.x >> 5);
    const int lane = threadIdx.x & 31;
    const int c    = lane * 4;
    const int kbeg = wg * EPW;
    if (kbeg >= num_edges) return;
    const int kend = min(kbeg + EPW, num_edges);

    int cur = __ldg(&seg_i[kbeg]);
    const int first_atom = cur;
    float4 acc = make_float4(0.f, 0.f, 0.f, 0.f);

    int k = kbeg;
    int j[GRP], s[GRP];
    int gsz = min(GRP, kend - k);
#pragma unroll
    for (int u = 0; u < GRP; u++)
        if (u < gsz) { j[u] = __ldg(&idx_j[k + u]); s[u] = __ldg(&seg_i[k + u]); }

    while (k < kend) {
        // prefetch next group's indices/segments
        int nj[GRP], ns[GRP];
        const int nk = k + GRP;
        const int ngsz = (nk < kend) ? min(GRP, kend - nk) : 0;
#pragma unroll
        for (int u = 0; u < GRP; u++)
            if (u < ngsz) { nj[u] = __ldg(&idx_j[nk + u]); ns[u] = __ldg(&seg_i[nk + u]); }

        // load this group's w and f interleaved in edge order (measured-best)
        float4 w4[GRP], f4[GRP];
#pragma unroll
        for (int u = 0; u < GRP; u++) {
            if (u < gsz) {
                w4[u] = __ldcs(reinterpret_cast<const float4*>(&w_ij[(size_t)(k + u) * 128 + c]));
                f4[u] = __ldg(reinterpret_cast<const float4*>(&g_f[(size_t)j[u] * 128 + c]));
            }
        }

        // accumulate with run-break flushes (seg uniform across warp)
#pragma unroll
        for (int u = 0; u < GRP; u++) {
            if (u < gsz) {
                acc.x = fmaf(w4[u].x, f4[u].x, acc.x);
                acc.y = fmaf(w4[u].y, f4[u].y, acc.y);
                acc.z = fmaf(w4[u].z, f4[u].z, acc.z);
                acc.w = fmaf(w4[u].w, f4[u].w, acc.w);
                int nxt = -1;
                if (u + 1 < gsz)      nxt = s[u + 1];
                else if (ngsz > 0)    nxt = ns[0];
                if (nxt != cur) {
                    if (nxt >= 0) {
                        flush_row(cur, c, acc, cur == first_atom);
                        acc = make_float4(0.f, 0.f, 0.f, 0.f);
                        cur = nxt;
                    }
                }
            }
        }

#pragma unroll
        for (int u = 0; u < GRP; u++) { j[u] = nj[u]; s[u] = ns[u]; }
        k = nk;
        gsz = ngsz;
    }

    // final flush: atom may span into neighboring chunks
    flush_row(cur, c, acc, true);
}

// ---------------------------------------------------------------------------
extern "C" void kernel_launch(void* const* d_in, const int* in_sizes, int n_in,
                              void* d_out, int out_size)
{
    const float* x    = (const float*)d_in[0];
    const float* wij  = (const float*)d_in[1];
    const int*   seg  = (const int*)d_in[2];
    const int*   idxj = (const int*)d_in[3];
    int base = 4;
    if (n_in >= 8 && in_sizes[4] == 1) base = 5;   // skip scalar seg_i_sum
    const float* Win  = (const float*)d_in[base];
    const float* Wout = (const float*)d_in[base + 1];
    const float* bout = (const float*)d_in[base + 2];

    int num_edges = in_sizes[2];
    int num_atoms = out_size / NFM;
    if (num_atoms > MAX_ATOMS) num_atoms = MAX_ATOMS;
    if (num_edges > MAX_EDGES) num_edges = MAX_EDGES;

    float*    f_ptr    = nullptr;
    float*    conv_ptr = nullptr;
    uint32_t* bfrag    = nullptr;
    cudaGetSymbolAddress((void**)&f_ptr, g_f);
    cudaGetSymbolAddress((void**)&conv_ptr, g_conv);
    cudaGetSymbolAddress((void**)&bfrag, g_Bfrag);

    const int SMEM_A = 2 * 64 * A_STRIDE * (int)sizeof(__nv_bfloat16);  // 34816
    cudaFuncSetAttribute(gemm_mma_kernel,
                         cudaFuncAttributeMaxDynamicSharedMemorySize, SMEM_A);

    int gblocks = (num_atoms + 63) / 64;

    // 0) pack weights + zero conv accumulator (one fused launch)
    int nf4 = num_atoms * 32;
    prep_zero_kernel<<<128 + (nf4 + 255) / 256, 256>>>(Win, Wout, nf4);

    // 1) f = x @ W_in
    gemm_mma_kernel<<<gblocks, 256, SMEM_A>>>(
        x, bfrag + 0 * 8192, bfrag + 1 * 8192, nullptr, f_ptr, num_atoms);

    // 2) conv = segment_sum(w_ij * f[idx_j])   (edge-centric, R9 config)
    int nwarps = (num_edges + EPW - 1) / EPW;
    conv_edge_kernel<<<(nwarps + 7) / 8, 256>>>(wij, idxj, seg, num_edges);

    // 3) out = conv @ W_out + b_out
    gemm_mma_kernel<<<gblocks, 256, SMEM_A>>>(
        conv_ptr, bfrag + 2 * 8192, bfrag + 3 * 8192, bout, (float*)d_out, num_atoms);
}

// round 17
// speedup vs baseline: 1.2265x; 1.0618x over previous
#include <cuda_runtime.h>
#include <cuda_bf16.h>
#include <cstdint>

#define MAX_ATOMS 40000
#define MAX_EDGES 640000
#define NFM 128

// ---------------------------------------------------------------------------
// Scratch
// ---------------------------------------------------------------------------
__device__ float    g_f[(size_t)MAX_ATOMS * NFM];     // f = x @ W_in
__device__ float    g_conv[(size_t)MAX_ATOMS * NFM];  // segment-summed conv
// Pre-packed B fragments in mma.m16n8k16 register order.
// [matrix: 0=Win 1=Wout][term: 0=hi 1=lo][ ((t*8+k)*32+lane)*2 + reg ]
__device__ uint32_t g_Bfrag[2][2][8192];

// ---------------------------------------------------------------------------
__device__ __forceinline__ void split_pair(float v0, float v1,
                                           uint32_t& hp, uint32_t& lp) {
    __nv_bfloat16 h0 = __float2bfloat16(v0);
    __nv_bfloat16 h1 = __float2bfloat16(v1);
    __nv_bfloat16 l0 = __float2bfloat16(v0 - __bfloat162float(h0));
    __nv_bfloat16 l1 = __float2bfloat16(v1 - __bfloat162float(h1));
    hp = (uint32_t)__bfloat16_as_ushort(h0) | ((uint32_t)__bfloat16_as_ushort(h1) << 16);
    lp = (uint32_t)__bfloat16_as_ushort(l0) | ((uint32_t)__bfloat16_as_ushort(l1) << 16);
}

__device__ __forceinline__ void mma16816(float* c, const uint32_t* a,
                                         uint32_t b0, uint32_t b1) {
    asm volatile(
        "mma.sync.aligned.m16n8k16.row.col.f32.bf16.bf16.f32 "
        "{%0,%1,%2,%3}, {%4,%5,%6,%7}, {%8,%9}, {%0,%1,%2,%3};"
        : "+f"(c[0]), "+f"(c[1]), "+f"(c[2]), "+f"(c[3])
        : "r"(a[0]), "r"(a[1]), "r"(a[2]), "r"(a[3]), "r"(b0), "r"(b1));
}

__device__ __forceinline__ uint32_t smem_u32(const void* p) {
    uint32_t a;
    asm("{ .reg .u64 t; cvta.to.shared.u64 t, %1; cvt.u32.u64 %0, t; }"
        : "=r"(a) : "l"(p));
    return a;
}

// ldmatrix x4: loads full m16k16 bf16 A-fragment (4 regs) in one instruction.
__device__ __forceinline__ void ldmatrix_x4(uint32_t* r, uint32_t addr) {
    asm volatile("ldmatrix.sync.aligned.m8n8.x4.shared.b16 {%0,%1,%2,%3}, [%4];"
                 : "=r"(r[0]), "=r"(r[1]), "=r"(r[2]), "=r"(r[3])
                 : "r"(addr));
}

// ---------------------------------------------------------------------------
// Fused prep + zero: blocks [0,128) pack weights into B-fragment order
// (split hi/lo); blocks [128, ...) zero g_conv. One launch, overlapped.
// ---------------------------------------------------------------------------
__global__ void prep_zero_kernel(const float* __restrict__ W_in,
                                 const float* __restrict__ W_out,
                                 int n_float4)
{
    if (blockIdx.x < 128) {
        int id = blockIdx.x * 256 + threadIdx.x;      // 0..32767
        int reg  = id & 1;
        int lane = (id >> 1) & 31;
        int k    = (id >> 6) & 7;
        int t    = (id >> 9) & 15;
        int term = (id >> 13) & 1;
        int mat  = (id >> 14) & 1;

        const float* W = mat ? W_out : W_in;
        int kr = k * 16 + (lane & 3) * 2 + reg * 8;
        int n  = t * 8 + (lane >> 2);
        float v0 = W[(size_t)kr * 128 + n];
        float v1 = W[(size_t)(kr + 1) * 128 + n];
        uint32_t hp, lp;
        split_pair(v0, v1, hp, lp);
        g_Bfrag[mat][term][(((t * 8 + k) * 32) + lane) * 2 + reg] = term ? lp : hp;
    } else {
        int i = (blockIdx.x - 128) * 256 + threadIdx.x;
        if (i < n_float4)
            reinterpret_cast<float4*>(g_conv)[i] = make_float4(0.f, 0.f, 0.f, 0.f);
    }
}

// ---------------------------------------------------------------------------
// GEMM via mma.sync: C[M,128] = A[M,128] @ W[128,128] (+bias).
// Split bf16 3-term. CTA: 64x128 tile, 8 warps (warp tile 32x32), 3 CTAs/SM.
// A fragments via ldmatrix.x4; B fragments via LDG.64.
// ---------------------------------------------------------------------------
#define A_STRIDE 136   // bf16 elems per row (conflict-free for LDS & ldmatrix)

__global__ __launch_bounds__(256, 3)
void gemm_mma_kernel(const float* __restrict__ A,
                     const uint32_t* __restrict__ Bh,
                     const uint32_t* __restrict__ Bl,
                     const float* __restrict__ bias,
                     float* __restrict__ C, int M)
{
    extern __shared__ __nv_bfloat16 sA[];     // [2][64][A_STRIDE]
    __nv_bfloat16* Ah = sA;
    __nv_bfloat16* Al = sA + 64 * A_STRIDE;

    const int tid = threadIdx.x;
    const int m0  = blockIdx.x * 64;

    // ---- stage A tile with float4 loads (8 x LDG.128 per thread) ----
#pragma unroll
    for (int it = 0; it < 8; it++) {
        int p  = tid + it * 256;              // 0..2047 float4s
        int m  = p >> 5;                      // local row 0..63
        int kq = (p & 31) << 2;               // col (multiple of 4)
        float4 v = make_float4(0.f, 0.f, 0.f, 0.f);
        if (m0 + m < M)
            v = *reinterpret_cast<const float4*>(&A[(size_t)(m0 + m) * 128 + kq]);
        uint32_t hp0, lp0, hp1, lp1;
        split_pair(v.x, v.y, hp0, lp0);
        split_pair(v.z, v.w, hp1, lp1);
        *reinterpret_cast<uint2*>(&Ah[m * A_STRIDE + kq]) = make_uint2(hp0, hp1);
        *reinterpret_cast<uint2*>(&Al[m * A_STRIDE + kq]) = make_uint2(lp0, lp1);
    }
    __syncthreads();

    const int wid  = tid >> 5;
    const int lane = tid & 31;
    const int wm   = wid & 1;
    const int wn   = wid >> 1;
    const int g    = lane >> 2;
    const int tg   = lane & 3;

    // ldmatrix lane->address mapping (fixed across k; col advances 32B/step)
    const int lrow = (lane & 7) + ((lane >> 3) & 1) * 8;   // 0..15 within m16
    const int lcol = ((lane >> 4) & 1) * 8;                // 0 or 8 (k halves)
    uint32_t a_addr[2][2];                                 // [term][mf]
#pragma unroll
    for (int mf = 0; mf < 2; mf++) {
        int row = wm * 32 + mf * 16 + lrow;
        a_addr[0][mf] = smem_u32(&Ah[row * A_STRIDE + lcol]);
        a_addr[1][mf] = smem_u32(&Al[row * A_STRIDE + lcol]);
    }

    float acc[2][4][4];
#pragma unroll
    for (int mf = 0; mf < 2; mf++)
#pragma unroll
        for (int t4 = 0; t4 < 4; t4++)
#pragma unroll
            for (int i = 0; i < 4; i++) acc[mf][t4][i] = 0.f;

#pragma unroll
    for (int k = 0; k < 8; k++) {
        uint32_t ah[2][4], al[2][4];
#pragma unroll
        for (int mf = 0; mf < 2; mf++) {
            ldmatrix_x4(ah[mf], a_addr[0][mf] + k * 32);
            ldmatrix_x4(al[mf], a_addr[1][mf] + k * 32);
        }
#pragma unroll
        for (int t4 = 0; t4 < 4; t4++) {
            int fidx = (((wn * 4 + t4) * 8 + k) * 32 + lane) * 2;
            uint2 bh = *reinterpret_cast<const uint2*>(&Bh[fidx]);
            uint2 bl = *reinterpret_cast<const uint2*>(&Bl[fidx]);
#pragma unroll
            for (int mf = 0; mf < 2; mf++) {
                mma16816(acc[mf][t4], ah[mf], bh.x, bh.y);
                mma16816(acc[mf][t4], ah[mf], bl.x, bl.y);
                mma16816(acc[mf][t4], al[mf], bh.x, bh.y);
            }
        }
    }

#pragma unroll
    for (int t4 = 0; t4 < 4; t4++) {
        int col = wn * 32 + t4 * 8 + tg * 2;
        float b0 = bias ? __ldg(&bias[col])     : 0.f;
        float b1 = bias ? __ldg(&bias[col + 1]) : 0.f;
#pragma unroll
        for (int mf = 0; mf < 2; mf++) {
            int row = m0 + wm * 32 + mf * 16 + g;
            if (row < M) {
                float2 o0 = make_float2(acc[mf][t4][0] + b0, acc[mf][t4][1] + b1);
                *reinterpret_cast<float2*>(&C[(size_t)row * 128 + col]) = o0;
            }
            if (row + 8 < M) {
                float2 o1 = make_float2(acc[mf][t4][2] + b0, acc[mf][t4][3] + b1);
                *reinterpret_cast<float2*>(&C[(size_t)(row + 8) * 128 + col]) = o1;
            }
        }
    }
}

// ---------------------------------------------------------------------------
// Edge-centric conv: EXACT R9 configuration (measured local optimum).
// ---------------------------------------------------------------------------
#define EPW 32
#define GRP 4

__device__ __forceinline__ void flush_row(int atom, int c, const float4& acc,
                                          bool use_atomic)
{
    float* p = &g_conv[(size_t)atom * 128 + c];
    if (use_atomic) {
        atomicAdd(p + 0, acc.x);
        atomicAdd(p + 1, acc.y);
        atomicAdd(p + 2, acc.z);
        atomicAdd(p + 3, acc.w);
    } else {
        *reinterpret_cast<float4*>(p) = acc;
    }
}

__global__ __launch_bounds__(256)
void conv_edge_kernel(const float* __restrict__ w_ij,
                      const int* __restrict__ idx_j,
                      const int* __restrict__ seg_i,
                      int num_edges)
{
    const int wg   = blockIdx.x * 8 + (threadIdx.x >> 5);
    const int lane = threadIdx.x & 31;
    const int c    = lane * 4;
    const int kbeg = wg * EPW;
    if (kbeg >= num_edges) return;
    const int kend = min(kbeg + EPW, num_edges);

    int cur = __ldg(&seg_i[kbeg]);
    const int first_atom = cur;
    float4 acc = make_float4(0.f, 0.f, 0.f, 0.f);

    int k = kbeg;
    int j[GRP], s[GRP];
    int gsz = min(GRP, kend - k);
#pragma unroll
    for (int u = 0; u < GRP; u++)
        if (u < gsz) { j[u] = __ldg(&idx_j[k + u]); s[u] = __ldg(&seg_i[k + u]); }

    while (k < kend) {
        int nj[GRP], ns[GRP];
        const int nk = k + GRP;
        const int ngsz = (nk < kend) ? min(GRP, kend - nk) : 0;
#pragma unroll
        for (int u = 0; u < GRP; u++)
            if (u < ngsz) { nj[u] = __ldg(&idx_j[nk + u]); ns[u] = __ldg(&seg_i[nk + u]); }

        float4 w4[GRP], f4[GRP];
#pragma unroll
        for (int u = 0; u < GRP; u++) {
            if (u < gsz) {
                w4[u] = __ldcs(reinterpret_cast<const float4*>(&w_ij[(size_t)(k + u) * 128 + c]));
                f4[u] = __ldg(reinterpret_cast<const float4*>(&g_f[(size_t)j[u] * 128 + c]));
            }
        }

#pragma unroll
        for (int u = 0; u < GRP; u++) {
            if (u < gsz) {
                acc.x = fmaf(w4[u].x, f4[u].x, acc.x);
                acc.y = fmaf(w4[u].y, f4[u].y, acc.y);
                acc.z = fmaf(w4[u].z, f4[u].z, acc.z);
                acc.w = fmaf(w4[u].w, f4[u].w, acc.w);
                int nxt = -1;
                if (u + 1 < gsz)      nxt = s[u + 1];
                else if (ngsz > 0)    nxt = ns[0];
                if (nxt != cur) {
                    if (nxt >= 0) {
                        flush_row(cur, c, acc, cur == first_atom);
                        acc = make_float4(0.f, 0.f, 0.f, 0.f);
                        cur = nxt;
                    }
                }
            }
        }

#pragma unroll
        for (int u = 0; u < GRP; u++) { j[u] = nj[u]; s[u] = ns[u]; }
        k = nk;
        gsz = ngsz;
    }

    flush_row(cur, c, acc, true);
}

// ---------------------------------------------------------------------------
extern "C" void kernel_launch(void* const* d_in, const int* in_sizes, int n_in,
                              void* d_out, int out_size)
{
    const float* x    = (const float*)d_in[0];
    const float* wij  = (const float*)d_in[1];
    const int*   seg  = (const int*)d_in[2];
    const int*   idxj = (const int*)d_in[3];
    int base = 4;
    if (n_in >= 8 && in_sizes[4] == 1) base = 5;   // skip scalar seg_i_sum
    const float* Win  = (const float*)d_in[base];
    const float* Wout = (const float*)d_in[base + 1];
    const float* bout = (const float*)d_in[base + 2];

    int num_edges = in_sizes[2];
    int num_atoms = out_size / NFM;
    if (num_atoms > MAX_ATOMS) num_atoms = MAX_ATOMS;
    if (num_edges > MAX_EDGES) num_edges = MAX_EDGES;

    float*    f_ptr    = nullptr;
    float*    conv_ptr = nullptr;
    uint32_t* bfrag    = nullptr;
    cudaGetSymbolAddress((void**)&f_ptr, g_f);
    cudaGetSymbolAddress((void**)&conv_ptr, g_conv);
    cudaGetSymbolAddress((void**)&bfrag, g_Bfrag);

    const int SMEM_A = 2 * 64 * A_STRIDE * (int)sizeof(__nv_bfloat16);  // 34816
    cudaFuncSetAttribute(gemm_mma_kernel,
                         cudaFuncAttributeMaxDynamicSharedMemorySize, SMEM_A);

    int gblocks = (num_atoms + 63) / 64;

    // 0) pack weights + zero conv accumulator (one fused launch)
    int nf4 = num_atoms * 32;
    prep_zero_kernel<<<128 + (nf4 + 255) / 256, 256>>>(Win, Wout, nf4);

    // 1) f = x @ W_in
    gemm_mma_kernel<<<gblocks, 256, SMEM_A>>>(
        x, bfrag + 0 * 8192, bfrag + 1 * 8192, nullptr, f_ptr, num_atoms);

    // 2) conv = segment_sum(w_ij * f[idx_j])   (edge-centric, R9 config)
    int nwarps = (num_edges + EPW - 1) / EPW;
    conv_edge_kernel<<<(nwarps + 7) / 8, 256>>>(wij, idxj, seg, num_edges);

    // 3) out = conv @ W_out + b_out
    gemm_mma_kernel<<<gblocks, 256, SMEM_A>>>(
        conv_ptr, bfrag + 2 * 8192, bfrag + 3 * 8192, bout, (float*)d_out, num_atoms);
}